// round 15
// baseline (speedup 1.0000x reference)
#include <cuda_runtime.h>
#include <cuda_bf16.h>
#include <cstdint>
#include <cstddef>

// ---------------------------------------------------------------------------
// AttentionRefinementModule — mma.sync bf16 implicit-GEMM pipeline (sm_100
// baseline target; tcgen05 unavailable in harness).
// R13 (= R12 fixed): store basis restored to 128 + r*32 (R10-proven scheme;
// R12 broke it by storing at 64 + r*32 while reads assume +64 base with the
// +2-column shift). Pad-row zero set re-derived in that basis (468 rows +
// 128B front guard). 4 kernels total; stats inline in bn_apply.
// ---------------------------------------------------------------------------

#define B_    8
#define T_    128
#define NH_   8
#define CIN_  16
#define COUT_ 32
#define H_    32
#define W_    64
#define L_    2048
#define PW_   68            // padded width (x pad 2 each side)

__device__ float g_cum[(size_t)B_ * T_ * CIN_ * L_];   // 128 MB scratch
__device__ __nv_bfloat16 g_wp[2 * 25 * COUT_ * CIN_];  // hi/lo weight planes
__device__ float g_acc[16];
__device__ float g_cnt;

// ---- smem layout (bytes) --------------------------------------------------
#define OFF_BIAS  80       // 32 floats
#define OFF_PROJ  256      // 256 floats, transposed [oc][n]
#define OFF_MASK  1280     // 2048 bytes
#define OFF_W     3328     // 51200 B: [plane][tap][oc][ic] bf16
#define OFF_AHI   54528
#define APLANE    80640    // 128B front guard + rows 0..2515 (base 128)
#define OFF_ALO   (OFF_AHI + APLANE)
#define SMEM_TOTAL (OFF_AHI + 2 * APLANE)   // 215808

#define NTHREADS  384
#define NPADROWS  468      // rows (base-128) that staging never writes

// ---- PTX helpers ----------------------------------------------------------
__device__ __forceinline__ uint32_t smem_u32(const void* p) {
    uint32_t a;
    asm("{ .reg .u64 t; cvta.to.shared.u64 t, %1; cvt.u32.u64 %0, t; }"
        : "=r"(a) : "l"(p));
    return a;
}
__device__ __forceinline__ void ldsm4(uint32_t* r, uint32_t addr) {
    asm volatile("ldmatrix.sync.aligned.m8n8.x4.shared.b16 {%0,%1,%2,%3}, [%4];"
                 : "=r"(r[0]), "=r"(r[1]), "=r"(r[2]), "=r"(r[3]) : "r"(addr));
}
__device__ __forceinline__ void mma16816(float* c, const uint32_t* a,
                                         const uint32_t* b) {
    asm volatile(
        "mma.sync.aligned.m16n8k16.row.col.f32.bf16.bf16.f32 "
        "{%0,%1,%2,%3}, {%4,%5,%6,%7}, {%8,%9}, {%0,%1,%2,%3};"
        : "+f"(c[0]), "+f"(c[1]), "+f"(c[2]), "+f"(c[3])
        : "r"(a[0]), "r"(a[1]), "r"(a[2]), "r"(a[3]), "r"(b[0]), "r"(b[1]));
}

// ---------------------------------------------------------------------------
// K1 cumsum (blocks 0..255) + prep/wprep (block 256)
// ---------------------------------------------------------------------------
__global__ void cumsum_kernel(const float* __restrict__ prev,
                              const float* __restrict__ curr,
                              const int* __restrict__ mask,
                              const float* __restrict__ convw) {
    if (blockIdx.x == 256) {
        // ---- prep: zero accumulators + unmasked count ----
        __shared__ int scnt;
        int tid = threadIdx.x;
        if (tid == 0) scnt = 0;
        if (tid < 16) g_acc[tid] = 0.0f;
        __syncthreads();
        int c = 0;
        for (int i = tid; i < B_ * L_; i += 256) c += (mask[i] == 0);
        #pragma unroll
        for (int off = 16; off; off >>= 1)
            c += __shfl_xor_sync(0xffffffffu, c, off);
        if ((tid & 31) == 0) atomicAdd(&scnt, c);
        __syncthreads();
        if (tid == 0) g_cnt = fmaxf(128.0f * (float)scnt, 1.0f);
        // ---- wprep: weight split hi/lo, layout [plane][tap][oc][ic] ----
        for (int idx = tid; idx < 12800; idx += 256) {
            int oc = idx / 400;
            int r  = idx - oc * 400;
            int ic = r / 25;
            int k  = r - ic * 25;            // tap = ky*5+kx
            float w = convw[idx];
            __nv_bfloat16 wh = __float2bfloat16_rn(w);
            __nv_bfloat16 wl = __float2bfloat16_rn(w - __bfloat162float(wh));
            g_wp[(k * 32 + oc) * 16 + ic] = wh;
            g_wp[12800 + (k * 32 + oc) * 16 + ic] = wl;
        }
        return;
    }
    int tid = blockIdx.x * blockDim.x + threadIdx.x;
    int b   = tid >> 13;
    int r   = tid & 8191;
    int ch  = r >> 9;
    int l4  = r & 511;
    const float* src0 = (ch < 8)
        ? prev + (size_t)(b * 8 + ch) * T_ * L_
        : curr + (size_t)(b * 8 + (ch - 8)) * T_ * L_;
    const float4* src = reinterpret_cast<const float4*>(src0) + l4;
    float4* dst = reinterpret_cast<float4*>(
        g_cum + ((size_t)(b * T_) * CIN_ + ch) * L_) + l4;
    float4 run = make_float4(0.f, 0.f, 0.f, 0.f);
    float4 nxt = src[0];
    for (int t = 0; t < T_; t++) {
        float4 cur = nxt;
        if (t < T_ - 1) nxt = src[(size_t)(t + 1) * (L_ / 4)];
        dst[(size_t)t * (CIN_ * L_ / 4)] = run;
        run.x += cur.x; run.y += cur.y; run.z += cur.z; run.w += cur.w;
    }
}

// ---------------------------------------------------------------------------
// K2 conv via mma.sync bf16 implicit GEMM. 384 threads, M=96 per chunk.
// Ext pixel grid: q in [0,2208), q = oy*68+ox+2 valid for oy<32, 2<=xe<66.
// Pixel (y,x) stored at plane + 128 + ((y+2)*68 + x+2)*32.
// A read for (q, ky, kx) at plane + 64 + (q + ky*68 + kx)*32  (== store of
// pixel (oy+ky-2, ox+kx-2); the +2-col shift cancels the 64B base delta).
// Staging writes rows 68k+2..68k+65 for k in [2,34); zero set = front 128B
// + rows {0..135} u {68k+{0,1,66,67}: k in [2,34)} u {2312..2515}.
// ---------------------------------------------------------------------------
__global__ void __launch_bounds__(NTHREADS)
conv_kernel(const float* __restrict__ convb,
            const float* __restrict__ projw,
            const int* __restrict__ mask,
            float* __restrict__ out) {
    extern __shared__ char sm[];
    uint32_t sb = smem_u32(sm);
    int tid = threadIdx.x;
    int wid = tid >> 5;
    int lane = tid & 31;
    int bt = blockIdx.x;
    int b  = bt >> 7;
    int t  = bt & 127;

    float* sBias  = reinterpret_cast<float*>(sm + OFF_BIAS);
    float* sProjT = reinterpret_cast<float*>(sm + OFF_PROJ);
    unsigned char* sMask = reinterpret_cast<unsigned char*>(sm + OFF_MASK);

    // ---- staging (single sync at the end; zero-set and stage-set disjoint)
    int4 z4 = make_int4(0, 0, 0, 0);
    // zero the pad rows of both planes (base 128)
    for (int i = tid; i < NPADROWS; i += NTHREADS) {
        int row;
        if (i < 136)      row = i;
        else if (i < 340) row = 2312 + (i - 136);   // 204 rows: 2312..2515
        else {
            int j = i - 340;                        // 128 rows
            int kk = (j >> 2) + 2;
            int m  = j & 3;
            row = 68 * kk + (m < 2 ? m : 64 + m);
        }
        int4* ph = reinterpret_cast<int4*>(sm + OFF_AHI + 128 + row * 32);
        int4* pl = reinterpret_cast<int4*>(sm + OFF_ALO + 128 + row * 32);
        ph[0] = z4; ph[1] = z4;
        pl[0] = z4; pl[1] = z4;
    }
    // zero the 128B front guards of both planes
    if (tid < 16) {
        int4* g = reinterpret_cast<int4*>(
            sm + (tid < 8 ? OFF_AHI : OFF_ALO) + (tid & 7) * 16);
        g[0] = z4;
    }
    {
        const int4* src = reinterpret_cast<const int4*>(g_wp);
        int4* dst = reinterpret_cast<int4*>(sm + OFF_W);
        for (int j = tid; j < 3200; j += NTHREADS) dst[j] = src[j];
    }
    if (tid < 32) sBias[tid] = convb[tid];
    if (tid < 256) { // transpose proj to [oc][n]
        int n = tid >> 5, oc = tid & 31;
        sProjT[oc * 8 + n] = projw[tid];
    }
    for (int j = tid; j < L_; j += NTHREADS)
        sMask[j] = (mask[b * L_ + j] != 0) ? 1 : 0;

    // fp32 [ch][px] -> bf16 hi/lo channel-last padded image (interior rows)
    {
        const float* src = g_cum + (size_t)bt * CIN_ * L_;
        for (int px = tid; px < L_; px += NTHREADS) {
            uint32_t h[8], l[8];
            #pragma unroll
            for (int cp = 0; cp < 8; cp++) {
                float v0 = src[(2 * cp) * L_ + px];
                float v1 = src[(2 * cp + 1) * L_ + px];
                __nv_bfloat16 h0 = __float2bfloat16_rn(v0);
                __nv_bfloat16 h1 = __float2bfloat16_rn(v1);
                __nv_bfloat16 l0 = __float2bfloat16_rn(v0 - __bfloat162float(h0));
                __nv_bfloat16 l1 = __float2bfloat16_rn(v1 - __bfloat162float(h1));
                h[cp] = ((uint32_t)*reinterpret_cast<uint16_t*>(&h1) << 16)
                      | (uint32_t)*reinterpret_cast<uint16_t*>(&h0);
                l[cp] = ((uint32_t)*reinterpret_cast<uint16_t*>(&l1) << 16)
                      | (uint32_t)*reinterpret_cast<uint16_t*>(&l0);
            }
            int y = px >> 6, x = px & 63;
            int byteoff = 128 + ((y + 2) * PW_ + x + 2) * 32;
            uint4* dh = reinterpret_cast<uint4*>(sm + OFF_AHI + byteoff);
            uint4* dl = reinterpret_cast<uint4*>(sm + OFF_ALO + byteoff);
            dh[0] = make_uint4(h[0], h[1], h[2], h[3]);
            dh[1] = make_uint4(h[4], h[5], h[6], h[7]);
            dl[0] = make_uint4(l[0], l[1], l[2], l[3]);
            dl[1] = make_uint4(l[4], l[5], l[6], l[7]);
        }
    }
    __syncthreads();

    // ---- per-thread ldmatrix base addresses -------------------------------
    uint32_t aHiBase = sb + OFF_AHI + 64
                     + (uint32_t)(lane & 15) * 32 + (uint32_t)(lane >> 4) * 16;
    uint32_t aLoBase = aHiBase + APLANE;
    // B (x4 non-trans of [oc][ic] rows): {b0,b1} oc-octet0, {b0,b1} oc-octet1
    uint32_t wBase = sb + OFF_W
                   + (uint32_t)((lane & 7) + ((lane >> 4) << 3)) * 32
                   + (uint32_t)((lane >> 3) & 1) * 16;

    // ---- main loop: 23 chunks of M=96 (6 m16 tiles), warp-strided ---------
    #pragma unroll 1
    for (int p = wid; p < 23; p += 12) {
        int q0 = p * 96;
        float c[6][4][4];
        #pragma unroll
        for (int mi = 0; mi < 6; mi++)
            #pragma unroll
            for (int j = 0; j < 4; j++)
                #pragma unroll
                for (int r = 0; r < 4; r++) c[mi][j][r] = 0.f;

        uint32_t ah = aHiBase + (uint32_t)q0 * 32;
        uint32_t al = aLoBase + (uint32_t)q0 * 32;

        #pragma unroll
        for (int ky = 0; ky < 5; ky++) {
            #pragma unroll
            for (int kx = 0; kx < 5; kx++) {
                int k = ky * 5 + kx;
                uint32_t off = (uint32_t)(ky * PW_ + kx) * 32;
                uint32_t bh[2][4], bl[2][4];
                uint32_t wtap = wBase + (uint32_t)k * 1024;
                ldsm4(bh[0], wtap);
                ldsm4(bh[1], wtap + 512);
                ldsm4(bl[0], wtap + 25600);
                ldsm4(bl[1], wtap + 25600 + 512);
                #pragma unroll
                for (int mi = 0; mi < 6; mi++) {
                    uint32_t ahi[4], alo[4];
                    ldsm4(ahi, ah + off + (uint32_t)mi * 512);
                    ldsm4(alo, al + off + (uint32_t)mi * 512);
                    #pragma unroll
                    for (int oh = 0; oh < 2; oh++) {
                        // pass 1: ahi*bhi ; pass 2: alo*bhi ; pass 3: ahi*blo
                        mma16816(c[mi][oh * 2 + 0], ahi, bh[oh] + 0);
                        mma16816(c[mi][oh * 2 + 1], ahi, bh[oh] + 2);
                        mma16816(c[mi][oh * 2 + 0], alo, bh[oh] + 0);
                        mma16816(c[mi][oh * 2 + 1], alo, bh[oh] + 2);
                        mma16816(c[mi][oh * 2 + 0], ahi, bl[oh] + 0);
                        mma16816(c[mi][oh * 2 + 1], ahi, bl[oh] + 2);
                    }
                }
            }
        }

        // ---- epilogue: bias+relu+proj, quad-reduce, store -----------------
        #pragma unroll
        for (int mi = 0; mi < 6; mi++) {
            #pragma unroll
            for (int half = 0; half < 2; half++) {
                int row = (lane >> 2) + half * 8;
                int q = q0 + mi * 16 + row;
                int y = q / PW_;
                int xe = q - y * PW_;
                bool valid = (xe >= 2 && xe < 66 && y < 32);
                int px = y * 64 + (xe - 2);
                float v[8];
                #pragma unroll
                for (int n = 0; n < 8; n++) v[n] = 0.f;
                if (valid && !sMask[px]) {
                    #pragma unroll
                    for (int j = 0; j < 4; j++) {
                        #pragma unroll
                        for (int e = 0; e < 2; e++) {
                            int oc = 8 * j + (lane & 3) * 2 + e;
                            float rv = fmaxf(c[mi][j][half * 2 + e] + sBias[oc],
                                             0.f);
                            const float* pt = sProjT + oc * 8;
                            #pragma unroll
                            for (int n = 0; n < 8; n++)
                                v[n] = fmaf(pt[n], rv, v[n]);
                        }
                    }
                }
                #pragma unroll
                for (int n = 0; n < 8; n++) {
                    v[n] += __shfl_xor_sync(0xffffffffu, v[n], 1);
                    v[n] += __shfl_xor_sync(0xffffffffu, v[n], 2);
                }
                if (valid) {
                    int n0 = (lane & 3) * 2;
                    size_t o0 = (((size_t)(b * 8 + n0) * T_ + t) << 11) + px;
                    out[o0] = v[n0];
                    out[o0 + ((size_t)T_ << 11)] = v[n0 + 1];
                }
            }
        }
    }
}

// ---------------------------------------------------------------------------
// K2b: per-channel sum/sumsq over stored pre-BN output (masked entries are 0)
// ---------------------------------------------------------------------------
__global__ void sum_kernel(const float* __restrict__ out) {
    __shared__ float sred[2];
    int tid = threadIdx.x;
    int bk  = blockIdx.x;
    int n   = (bk >> 4) & 7;
    if (tid == 0) { sred[0] = 0.f; sred[1] = 0.f; }
    __syncthreads();
    const float4* p = reinterpret_cast<const float4*>(out) + (size_t)bk * 4096;
    float s = 0.f, sq = 0.f;
    for (int i = tid; i < 4096; i += 256) {
        float4 v = p[i];
        s  += v.x + v.y + v.z + v.w;
        sq += v.x * v.x + v.y * v.y + v.z * v.z + v.w * v.w;
    }
    #pragma unroll
    for (int off = 16; off; off >>= 1) {
        s  += __shfl_xor_sync(0xffffffffu, s, off);
        sq += __shfl_xor_sync(0xffffffffu, sq, off);
    }
    if ((tid & 31) == 0) {
        atomicAdd(&sred[0], s);
        atomicAdd(&sred[1], sq);
    }
    __syncthreads();
    if (tid == 0) {
        atomicAdd(&g_acc[n], sred[0]);
        atomicAdd(&g_acc[8 + n], sred[1]);
    }
}

// ---------------------------------------------------------------------------
// K4 BN apply (stats computed inline from g_acc/g_cnt)
// ---------------------------------------------------------------------------
__global__ void bn_apply_kernel(float* __restrict__ out,
                                const int* __restrict__ mask,
                                const float* __restrict__ gamma,
                                const float* __restrict__ beta) {
    int idx = blockIdx.x * 256 + threadIdx.x;
    int nlin = idx >> 16;
    int n = nlin & 7;
    int bb = nlin >> 3;
    int l4 = idx & 511;
    float cnt  = g_cnt;
    float mean = g_acc[n] / cnt;
    float var  = fmaxf(g_acc[8 + n] / cnt - mean * mean, 0.0f);
    float sc   = gamma[n] * rsqrtf(var + 1e-5f);
    float sh   = beta[n] - mean * sc;
    int4 m = *reinterpret_cast<const int4*>(mask + bb * L_ + l4 * 4);
    float4* p = reinterpret_cast<float4*>(out) + idx;
    float4 v = *p;
    v.x = m.x ? v.x : fmaf(v.x, sc, sh);
    v.y = m.y ? v.y : fmaf(v.y, sc, sh);
    v.z = m.z ? v.z : fmaf(v.z, sc, sh);
    v.w = m.w ? v.w : fmaf(v.w, sc, sh);
    *p = v;
}

// ---------------------------------------------------------------------------
extern "C" void kernel_launch(void* const* d_in, const int* in_sizes, int n_in,
                              void* d_out, int out_size) {
    const float* prev  = (const float*)d_in[0];
    const float* curr  = (const float*)d_in[1];
    const int*   mask  = (const int*)d_in[2];
    const float* convw = (const float*)d_in[4];
    const float* convb = (const float*)d_in[5];
    const float* projw = (const float*)d_in[6];
    const float* gamma = (const float*)d_in[7];
    const float* beta  = (const float*)d_in[8];
    float* out = (float*)d_out;

    cudaFuncSetAttribute(conv_kernel,
                         cudaFuncAttributeMaxDynamicSharedMemorySize,
                         SMEM_TOTAL);

    cumsum_kernel<<<257, 256>>>(prev, curr, mask, convw);
    conv_kernel<<<B_ * T_, NTHREADS, SMEM_TOTAL>>>(convb, projw, mask, out);
    sum_kernel<<<1024, 256>>>(out);
    bn_apply_kernel<<<(B_ * NH_ * T_ * L_ / 4) / 256, 256>>>(out, mask,
                                                             gamma, beta);
}

// round 16
// speedup vs baseline: 1.0023x; 1.0023x over previous
#include <cuda_runtime.h>
#include <cuda_bf16.h>
#include <cstdint>
#include <cstddef>

// ---------------------------------------------------------------------------
// AttentionRefinementModule — mma.sync bf16 implicit-GEMM pipeline (sm_100
// baseline target; tcgen05 unavailable in harness).
// R13 (= R12 fixed): store basis restored to 128 + r*32 (R10-proven scheme;
// R12 broke it by storing at 64 + r*32 while reads assume +64 base with the
// +2-column shift). Pad-row zero set re-derived in that basis (468 rows +
// 128B front guard). 4 kernels total; stats inline in bn_apply.
// ---------------------------------------------------------------------------

#define B_    8
#define T_    128
#define NH_   8
#define CIN_  16
#define COUT_ 32
#define H_    32
#define W_    64
#define L_    2048
#define PW_   68            // padded width (x pad 2 each side)

__device__ float g_cum[(size_t)B_ * T_ * CIN_ * L_];   // 128 MB scratch
__device__ __nv_bfloat16 g_wp[2 * 25 * COUT_ * CIN_];  // hi/lo weight planes
__device__ float g_acc[16];
__device__ float g_cnt;

// ---- smem layout (bytes) --------------------------------------------------
#define OFF_BIAS  80       // 32 floats
#define OFF_PROJ  256      // 256 floats, transposed [oc][n]
#define OFF_MASK  1280     // 2048 bytes
#define OFF_W     3328     // 51200 B: [plane][tap][oc][ic] bf16
#define OFF_AHI   54528
#define APLANE    80640    // 128B front guard + rows 0..2515 (base 128)
#define OFF_ALO   (OFF_AHI + APLANE)
#define SMEM_TOTAL (OFF_AHI + 2 * APLANE)   // 215808

#define NTHREADS  384
#define NPADROWS  468      // rows (base-128) that staging never writes

// ---- PTX helpers ----------------------------------------------------------
__device__ __forceinline__ uint32_t smem_u32(const void* p) {
    uint32_t a;
    asm("{ .reg .u64 t; cvta.to.shared.u64 t, %1; cvt.u32.u64 %0, t; }"
        : "=r"(a) : "l"(p));
    return a;
}
__device__ __forceinline__ void ldsm4(uint32_t* r, uint32_t addr) {
    asm volatile("ldmatrix.sync.aligned.m8n8.x4.shared.b16 {%0,%1,%2,%3}, [%4];"
                 : "=r"(r[0]), "=r"(r[1]), "=r"(r[2]), "=r"(r[3]) : "r"(addr));
}
__device__ __forceinline__ void mma16816(float* c, const uint32_t* a,
                                         const uint32_t* b) {
    asm volatile(
        "mma.sync.aligned.m16n8k16.row.col.f32.bf16.bf16.f32 "
        "{%0,%1,%2,%3}, {%4,%5,%6,%7}, {%8,%9}, {%0,%1,%2,%3};"
        : "+f"(c[0]), "+f"(c[1]), "+f"(c[2]), "+f"(c[3])
        : "r"(a[0]), "r"(a[1]), "r"(a[2]), "r"(a[3]), "r"(b[0]), "r"(b[1]));
}

// ---------------------------------------------------------------------------
// K1 cumsum (blocks 0..255) + prep/wprep (block 256)
// ---------------------------------------------------------------------------
__global__ void cumsum_kernel(const float* __restrict__ prev,
                              const float* __restrict__ curr,
                              const int* __restrict__ mask,
                              const float* __restrict__ convw) {
    if (blockIdx.x == 256) {
        // ---- prep: zero accumulators + unmasked count ----
        __shared__ int scnt;
        int tid = threadIdx.x;
        if (tid == 0) scnt = 0;
        if (tid < 16) g_acc[tid] = 0.0f;
        __syncthreads();
        int c = 0;
        for (int i = tid; i < B_ * L_; i += 256) c += (mask[i] == 0);
        #pragma unroll
        for (int off = 16; off; off >>= 1)
            c += __shfl_xor_sync(0xffffffffu, c, off);
        if ((tid & 31) == 0) atomicAdd(&scnt, c);
        __syncthreads();
        if (tid == 0) g_cnt = fmaxf(128.0f * (float)scnt, 1.0f);
        // ---- wprep: weight split hi/lo, layout [plane][tap][oc][ic] ----
        for (int idx = tid; idx < 12800; idx += 256) {
            int oc = idx / 400;
            int r  = idx - oc * 400;
            int ic = r / 25;
            int k  = r - ic * 25;            // tap = ky*5+kx
            float w = convw[idx];
            __nv_bfloat16 wh = __float2bfloat16_rn(w);
            __nv_bfloat16 wl = __float2bfloat16_rn(w - __bfloat162float(wh));
            g_wp[(k * 32 + oc) * 16 + ic] = wh;
            g_wp[12800 + (k * 32 + oc) * 16 + ic] = wl;
        }
        return;
    }
    int tid = blockIdx.x * blockDim.x + threadIdx.x;
    int b   = tid >> 13;
    int r   = tid & 8191;
    int ch  = r >> 9;
    int l4  = r & 511;
    const float* src0 = (ch < 8)
        ? prev + (size_t)(b * 8 + ch) * T_ * L_
        : curr + (size_t)(b * 8 + (ch - 8)) * T_ * L_;
    const float4* src = reinterpret_cast<const float4*>(src0) + l4;
    float4* dst = reinterpret_cast<float4*>(
        g_cum + ((size_t)(b * T_) * CIN_ + ch) * L_) + l4;
    float4 run = make_float4(0.f, 0.f, 0.f, 0.f);
    float4 nxt = src[0];
    for (int t = 0; t < T_; t++) {
        float4 cur = nxt;
        if (t < T_ - 1) nxt = src[(size_t)(t + 1) * (L_ / 4)];
        dst[(size_t)t * (CIN_ * L_ / 4)] = run;
        run.x += cur.x; run.y += cur.y; run.z += cur.z; run.w += cur.w;
    }
}

// ---------------------------------------------------------------------------
// K2 conv via mma.sync bf16 implicit GEMM. 384 threads, M=96 per chunk.
// Ext pixel grid: q in [0,2208), q = oy*68+ox+2 valid for oy<32, 2<=xe<66.
// Pixel (y,x) stored at plane + 128 + ((y+2)*68 + x+2)*32.
// A read for (q, ky, kx) at plane + 64 + (q + ky*68 + kx)*32  (== store of
// pixel (oy+ky-2, ox+kx-2); the +2-col shift cancels the 64B base delta).
// Staging writes rows 68k+2..68k+65 for k in [2,34); zero set = front 128B
// + rows {0..135} u {68k+{0,1,66,67}: k in [2,34)} u {2312..2515}.
// ---------------------------------------------------------------------------
__global__ void __launch_bounds__(NTHREADS)
conv_kernel(const float* __restrict__ convb,
            const float* __restrict__ projw,
            const int* __restrict__ mask,
            float* __restrict__ out) {
    extern __shared__ char sm[];
    uint32_t sb = smem_u32(sm);
    int tid = threadIdx.x;
    int wid = tid >> 5;
    int lane = tid & 31;
    int bt = blockIdx.x;
    int b  = bt >> 7;
    int t  = bt & 127;

    float* sBias  = reinterpret_cast<float*>(sm + OFF_BIAS);
    float* sProjT = reinterpret_cast<float*>(sm + OFF_PROJ);
    unsigned char* sMask = reinterpret_cast<unsigned char*>(sm + OFF_MASK);

    // ---- staging (single sync at the end; zero-set and stage-set disjoint)
    int4 z4 = make_int4(0, 0, 0, 0);
    // zero the pad rows of both planes (base 128)
    for (int i = tid; i < NPADROWS; i += NTHREADS) {
        int row;
        if (i < 136)      row = i;
        else if (i < 340) row = 2312 + (i - 136);   // 204 rows: 2312..2515
        else {
            int j = i - 340;                        // 128 rows
            int kk = (j >> 2) + 2;
            int m  = j & 3;
            row = 68 * kk + (m < 2 ? m : 64 + m);
        }
        int4* ph = reinterpret_cast<int4*>(sm + OFF_AHI + 128 + row * 32);
        int4* pl = reinterpret_cast<int4*>(sm + OFF_ALO + 128 + row * 32);
        ph[0] = z4; ph[1] = z4;
        pl[0] = z4; pl[1] = z4;
    }
    // zero the 128B front guards of both planes
    if (tid < 16) {
        int4* g = reinterpret_cast<int4*>(
            sm + (tid < 8 ? OFF_AHI : OFF_ALO) + (tid & 7) * 16);
        g[0] = z4;
    }
    {
        const int4* src = reinterpret_cast<const int4*>(g_wp);
        int4* dst = reinterpret_cast<int4*>(sm + OFF_W);
        for (int j = tid; j < 3200; j += NTHREADS) dst[j] = src[j];
    }
    if (tid < 32) sBias[tid] = convb[tid];
    if (tid < 256) { // transpose proj to [oc][n]
        int n = tid >> 5, oc = tid & 31;
        sProjT[oc * 8 + n] = projw[tid];
    }
    for (int j = tid; j < L_; j += NTHREADS)
        sMask[j] = (mask[b * L_ + j] != 0) ? 1 : 0;

    // fp32 [ch][px] -> bf16 hi/lo channel-last padded image (interior rows)
    {
        const float* src = g_cum + (size_t)bt * CIN_ * L_;
        for (int px = tid; px < L_; px += NTHREADS) {
            uint32_t h[8], l[8];
            #pragma unroll
            for (int cp = 0; cp < 8; cp++) {
                float v0 = src[(2 * cp) * L_ + px];
                float v1 = src[(2 * cp + 1) * L_ + px];
                __nv_bfloat16 h0 = __float2bfloat16_rn(v0);
                __nv_bfloat16 h1 = __float2bfloat16_rn(v1);
                __nv_bfloat16 l0 = __float2bfloat16_rn(v0 - __bfloat162float(h0));
                __nv_bfloat16 l1 = __float2bfloat16_rn(v1 - __bfloat162float(h1));
                h[cp] = ((uint32_t)*reinterpret_cast<uint16_t*>(&h1) << 16)
                      | (uint32_t)*reinterpret_cast<uint16_t*>(&h0);
                l[cp] = ((uint32_t)*reinterpret_cast<uint16_t*>(&l1) << 16)
                      | (uint32_t)*reinterpret_cast<uint16_t*>(&l0);
            }
            int y = px >> 6, x = px & 63;
            int byteoff = 128 + ((y + 2) * PW_ + x + 2) * 32;
            uint4* dh = reinterpret_cast<uint4*>(sm + OFF_AHI + byteoff);
            uint4* dl = reinterpret_cast<uint4*>(sm + OFF_ALO + byteoff);
            dh[0] = make_uint4(h[0], h[1], h[2], h[3]);
            dh[1] = make_uint4(h[4], h[5], h[6], h[7]);
            dl[0] = make_uint4(l[0], l[1], l[2], l[3]);
            dl[1] = make_uint4(l[4], l[5], l[6], l[7]);
        }
    }
    __syncthreads();

    // ---- per-thread ldmatrix base addresses -------------------------------
    uint32_t aHiBase = sb + OFF_AHI + 64
                     + (uint32_t)(lane & 15) * 32 + (uint32_t)(lane >> 4) * 16;
    uint32_t aLoBase = aHiBase + APLANE;
    // B (x4 non-trans of [oc][ic] rows): {b0,b1} oc-octet0, {b0,b1} oc-octet1
    uint32_t wBase = sb + OFF_W
                   + (uint32_t)((lane & 7) + ((lane >> 4) << 3)) * 32
                   + (uint32_t)((lane >> 3) & 1) * 16;

    // ---- main loop: 23 chunks of M=96 (6 m16 tiles), warp-strided ---------
    #pragma unroll 1
    for (int p = wid; p < 23; p += 12) {
        int q0 = p * 96;
        float c[6][4][4];
        #pragma unroll
        for (int mi = 0; mi < 6; mi++)
            #pragma unroll
            for (int j = 0; j < 4; j++)
                #pragma unroll
                for (int r = 0; r < 4; r++) c[mi][j][r] = 0.f;

        uint32_t ah = aHiBase + (uint32_t)q0 * 32;
        uint32_t al = aLoBase + (uint32_t)q0 * 32;

        #pragma unroll
        for (int ky = 0; ky < 5; ky++) {
            #pragma unroll
            for (int kx = 0; kx < 5; kx++) {
                int k = ky * 5 + kx;
                uint32_t off = (uint32_t)(ky * PW_ + kx) * 32;
                uint32_t bh[2][4], bl[2][4];
                uint32_t wtap = wBase + (uint32_t)k * 1024;
                ldsm4(bh[0], wtap);
                ldsm4(bh[1], wtap + 512);
                ldsm4(bl[0], wtap + 25600);
                ldsm4(bl[1], wtap + 25600 + 512);
                #pragma unroll
                for (int mi = 0; mi < 6; mi++) {
                    uint32_t ahi[4], alo[4];
                    ldsm4(ahi, ah + off + (uint32_t)mi * 512);
                    ldsm4(alo, al + off + (uint32_t)mi * 512);
                    #pragma unroll
                    for (int oh = 0; oh < 2; oh++) {
                        // pass 1: ahi*bhi ; pass 2: alo*bhi ; pass 3: ahi*blo
                        mma16816(c[mi][oh * 2 + 0], ahi, bh[oh] + 0);
                        mma16816(c[mi][oh * 2 + 1], ahi, bh[oh] + 2);
                        mma16816(c[mi][oh * 2 + 0], alo, bh[oh] + 0);
                        mma16816(c[mi][oh * 2 + 1], alo, bh[oh] + 2);
                        mma16816(c[mi][oh * 2 + 0], ahi, bl[oh] + 0);
                        mma16816(c[mi][oh * 2 + 1], ahi, bl[oh] + 2);
                    }
                }
            }
        }

        // ---- epilogue: bias+relu+proj, quad-reduce, store -----------------
        #pragma unroll
        for (int mi = 0; mi < 6; mi++) {
            #pragma unroll
            for (int half = 0; half < 2; half++) {
                int row = (lane >> 2) + half * 8;
                int q = q0 + mi * 16 + row;
                int y = q / PW_;
                int xe = q - y * PW_;
                bool valid = (xe >= 2 && xe < 66 && y < 32);
                int px = y * 64 + (xe - 2);
                float v[8];
                #pragma unroll
                for (int n = 0; n < 8; n++) v[n] = 0.f;
                if (valid && !sMask[px]) {
                    #pragma unroll
                    for (int j = 0; j < 4; j++) {
                        #pragma unroll
                        for (int e = 0; e < 2; e++) {
                            int oc = 8 * j + (lane & 3) * 2 + e;
                            float rv = fmaxf(c[mi][j][half * 2 + e] + sBias[oc],
                                             0.f);
                            const float* pt = sProjT + oc * 8;
                            #pragma unroll
                            for (int n = 0; n < 8; n++)
                                v[n] = fmaf(pt[n], rv, v[n]);
                        }
                    }
                }
                #pragma unroll
                for (int n = 0; n < 8; n++) {
                    v[n] += __shfl_xor_sync(0xffffffffu, v[n], 1);
                    v[n] += __shfl_xor_sync(0xffffffffu, v[n], 2);
                }
                if (valid) {
                    int n0 = (lane & 3) * 2;
                    size_t o0 = (((size_t)(b * 8 + n0) * T_ + t) << 11) + px;
                    out[o0] = v[n0];
                    out[o0 + ((size_t)T_ << 11)] = v[n0 + 1];
                }
            }
        }
    }
}

// ---------------------------------------------------------------------------
// K2b: per-channel sum/sumsq over stored pre-BN output (masked entries are 0)
// ---------------------------------------------------------------------------
__global__ void sum_kernel(const float* __restrict__ out) {
    __shared__ float sred[2];
    int tid = threadIdx.x;
    int bk  = blockIdx.x;
    int n   = (bk >> 4) & 7;
    if (tid == 0) { sred[0] = 0.f; sred[1] = 0.f; }
    __syncthreads();
    const float4* p = reinterpret_cast<const float4*>(out) + (size_t)bk * 4096;
    float s = 0.f, sq = 0.f;
    for (int i = tid; i < 4096; i += 256) {
        float4 v = p[i];
        s  += v.x + v.y + v.z + v.w;
        sq += v.x * v.x + v.y * v.y + v.z * v.z + v.w * v.w;
    }
    #pragma unroll
    for (int off = 16; off; off >>= 1) {
        s  += __shfl_xor_sync(0xffffffffu, s, off);
        sq += __shfl_xor_sync(0xffffffffu, sq, off);
    }
    if ((tid & 31) == 0) {
        atomicAdd(&sred[0], s);
        atomicAdd(&sred[1], sq);
    }
    __syncthreads();
    if (tid == 0) {
        atomicAdd(&g_acc[n], sred[0]);
        atomicAdd(&g_acc[8 + n], sred[1]);
    }
}

// ---------------------------------------------------------------------------
// K4 BN apply (stats computed inline from g_acc/g_cnt)
// ---------------------------------------------------------------------------
__global__ void bn_apply_kernel(float* __restrict__ out,
                                const int* __restrict__ mask,
                                const float* __restrict__ gamma,
                                const float* __restrict__ beta) {
    int idx = blockIdx.x * 256 + threadIdx.x;
    int nlin = idx >> 16;
    int n = nlin & 7;
    int bb = nlin >> 3;
    int l4 = idx & 511;
    float cnt  = g_cnt;
    float mean = g_acc[n] / cnt;
    float var  = fmaxf(g_acc[8 + n] / cnt - mean * mean, 0.0f);
    float sc   = gamma[n] * rsqrtf(var + 1e-5f);
    float sh   = beta[n] - mean * sc;
    int4 m = *reinterpret_cast<const int4*>(mask + bb * L_ + l4 * 4);
    float4* p = reinterpret_cast<float4*>(out) + idx;
    float4 v = *p;
    v.x = m.x ? v.x : fmaf(v.x, sc, sh);
    v.y = m.y ? v.y : fmaf(v.y, sc, sh);
    v.z = m.z ? v.z : fmaf(v.z, sc, sh);
    v.w = m.w ? v.w : fmaf(v.w, sc, sh);
    *p = v;
}

// ---------------------------------------------------------------------------
extern "C" void kernel_launch(void* const* d_in, const int* in_sizes, int n_in,
                              void* d_out, int out_size) {
    const float* prev  = (const float*)d_in[0];
    const float* curr  = (const float*)d_in[1];
    const int*   mask  = (const int*)d_in[2];
    const float* convw = (const float*)d_in[4];
    const float* convb = (const float*)d_in[5];
    const float* projw = (const float*)d_in[6];
    const float* gamma = (const float*)d_in[7];
    const float* beta  = (const float*)d_in[8];
    float* out = (float*)d_out;

    cudaFuncSetAttribute(conv_kernel,
                         cudaFuncAttributeMaxDynamicSharedMemorySize,
                         SMEM_TOTAL);

    cumsum_kernel<<<257, 256>>>(prev, curr, mask, convw);
    conv_kernel<<<B_ * T_, NTHREADS, SMEM_TOTAL>>>(convb, projw, mask, out);
    sum_kernel<<<1024, 256>>>(out);
    bn_apply_kernel<<<(B_ * NH_ * T_ * L_ / 4) / 256, 256>>>(out, mask,
                                                             gamma, beta);
}

// round 17
// speedup vs baseline: 1.0029x; 1.0006x over previous
#include <cuda_runtime.h>
#include <cuda_bf16.h>
#include <cstdint>
#include <cstddef>

// ---------------------------------------------------------------------------
// AttentionRefinementModule — mma.sync bf16 implicit-GEMM pipeline (sm_100
// baseline target; tcgen05 unavailable in harness).
// R17: mainloop latency attack. All asm is volatile => program order is
// fixed, so (a) reorder the 3 split passes pass-major (same-accumulator mma
// distance 2 -> 4), (b) double-buffer A fragments: issue mi+1's ldmatrix
// before mi's 12 mma to hide LDS latency behind the tensor block.
// Everything else identical to the passing R13 (626.6us).
// ---------------------------------------------------------------------------

#define B_    8
#define T_    128
#define NH_   8
#define CIN_  16
#define COUT_ 32
#define H_    32
#define W_    64
#define L_    2048
#define PW_   68            // padded width (x pad 2 each side)

__device__ float g_cum[(size_t)B_ * T_ * CIN_ * L_];   // 128 MB scratch
__device__ __nv_bfloat16 g_wp[2 * 25 * COUT_ * CIN_];  // hi/lo weight planes
__device__ float g_acc[16];
__device__ float g_cnt;

// ---- smem layout (bytes) --------------------------------------------------
#define OFF_BIAS  80       // 32 floats
#define OFF_PROJ  256      // 256 floats, transposed [oc][n]
#define OFF_MASK  1280     // 2048 bytes
#define OFF_W     3328     // 51200 B: [plane][tap][oc][ic] bf16
#define OFF_AHI   54528
#define APLANE    80640    // 128B front guard + rows 0..2515 (base 128)
#define OFF_ALO   (OFF_AHI + APLANE)
#define SMEM_TOTAL (OFF_AHI + 2 * APLANE)   // 215808

#define NTHREADS  384
#define NPADROWS  468      // rows (base-128) that staging never writes

// ---- PTX helpers ----------------------------------------------------------
__device__ __forceinline__ uint32_t smem_u32(const void* p) {
    uint32_t a;
    asm("{ .reg .u64 t; cvta.to.shared.u64 t, %1; cvt.u32.u64 %0, t; }"
        : "=r"(a) : "l"(p));
    return a;
}
__device__ __forceinline__ void ldsm4(uint32_t* r, uint32_t addr) {
    asm volatile("ldmatrix.sync.aligned.m8n8.x4.shared.b16 {%0,%1,%2,%3}, [%4];"
                 : "=r"(r[0]), "=r"(r[1]), "=r"(r[2]), "=r"(r[3]) : "r"(addr));
}
__device__ __forceinline__ void mma16816(float* c, const uint32_t* a,
                                         const uint32_t* b) {
    asm volatile(
        "mma.sync.aligned.m16n8k16.row.col.f32.bf16.bf16.f32 "
        "{%0,%1,%2,%3}, {%4,%5,%6,%7}, {%8,%9}, {%0,%1,%2,%3};"
        : "+f"(c[0]), "+f"(c[1]), "+f"(c[2]), "+f"(c[3])
        : "r"(a[0]), "r"(a[1]), "r"(a[2]), "r"(a[3]), "r"(b[0]), "r"(b[1]));
}

// ---------------------------------------------------------------------------
// K1 cumsum (blocks 0..255) + prep/wprep (block 256)
// ---------------------------------------------------------------------------
__global__ void cumsum_kernel(const float* __restrict__ prev,
                              const float* __restrict__ curr,
                              const int* __restrict__ mask,
                              const float* __restrict__ convw) {
    if (blockIdx.x == 256) {
        // ---- prep: zero accumulators + unmasked count ----
        __shared__ int scnt;
        int tid = threadIdx.x;
        if (tid == 0) scnt = 0;
        if (tid < 16) g_acc[tid] = 0.0f;
        __syncthreads();
        int c = 0;
        for (int i = tid; i < B_ * L_; i += 256) c += (mask[i] == 0);
        #pragma unroll
        for (int off = 16; off; off >>= 1)
            c += __shfl_xor_sync(0xffffffffu, c, off);
        if ((tid & 31) == 0) atomicAdd(&scnt, c);
        __syncthreads();
        if (tid == 0) g_cnt = fmaxf(128.0f * (float)scnt, 1.0f);
        // ---- wprep: weight split hi/lo, layout [plane][tap][oc][ic] ----
        for (int idx = tid; idx < 12800; idx += 256) {
            int oc = idx / 400;
            int r  = idx - oc * 400;
            int ic = r / 25;
            int k  = r - ic * 25;            // tap = ky*5+kx
            float w = convw[idx];
            __nv_bfloat16 wh = __float2bfloat16_rn(w);
            __nv_bfloat16 wl = __float2bfloat16_rn(w - __bfloat162float(wh));
            g_wp[(k * 32 + oc) * 16 + ic] = wh;
            g_wp[12800 + (k * 32 + oc) * 16 + ic] = wl;
        }
        return;
    }
    int tid = blockIdx.x * blockDim.x + threadIdx.x;
    int b   = tid >> 13;
    int r   = tid & 8191;
    int ch  = r >> 9;
    int l4  = r & 511;
    const float* src0 = (ch < 8)
        ? prev + (size_t)(b * 8 + ch) * T_ * L_
        : curr + (size_t)(b * 8 + (ch - 8)) * T_ * L_;
    const float4* src = reinterpret_cast<const float4*>(src0) + l4;
    float4* dst = reinterpret_cast<float4*>(
        g_cum + ((size_t)(b * T_) * CIN_ + ch) * L_) + l4;
    float4 run = make_float4(0.f, 0.f, 0.f, 0.f);
    float4 nxt = src[0];
    for (int t = 0; t < T_; t++) {
        float4 cur = nxt;
        if (t < T_ - 1) nxt = src[(size_t)(t + 1) * (L_ / 4)];
        dst[(size_t)t * (CIN_ * L_ / 4)] = run;
        run.x += cur.x; run.y += cur.y; run.z += cur.z; run.w += cur.w;
    }
}

// ---------------------------------------------------------------------------
// K2 conv via mma.sync bf16 implicit GEMM. 384 threads, M=96 per chunk.
// Ext pixel grid: q in [0,2208), q = oy*68+ox+2 valid for oy<32, 2<=xe<66.
// Pixel (y,x) stored at plane + 128 + ((y+2)*68 + x+2)*32.
// A read for (q, ky, kx) at plane + 64 + (q + ky*68 + kx)*32.
// ---------------------------------------------------------------------------
__global__ void __launch_bounds__(NTHREADS)
conv_kernel(const float* __restrict__ convb,
            const float* __restrict__ projw,
            const int* __restrict__ mask,
            float* __restrict__ out) {
    extern __shared__ char sm[];
    uint32_t sb = smem_u32(sm);
    int tid = threadIdx.x;
    int wid = tid >> 5;
    int lane = tid & 31;
    int bt = blockIdx.x;
    int b  = bt >> 7;
    int t  = bt & 127;

    float* sBias  = reinterpret_cast<float*>(sm + OFF_BIAS);
    float* sProjT = reinterpret_cast<float*>(sm + OFF_PROJ);
    unsigned char* sMask = reinterpret_cast<unsigned char*>(sm + OFF_MASK);

    // ---- staging (single sync at the end; zero-set and stage-set disjoint)
    int4 z4 = make_int4(0, 0, 0, 0);
    for (int i = tid; i < NPADROWS; i += NTHREADS) {
        int row;
        if (i < 136)      row = i;
        else if (i < 340) row = 2312 + (i - 136);   // 204 rows: 2312..2515
        else {
            int j = i - 340;                        // 128 rows
            int kk = (j >> 2) + 2;
            int m  = j & 3;
            row = 68 * kk + (m < 2 ? m : 64 + m);
        }
        int4* ph = reinterpret_cast<int4*>(sm + OFF_AHI + 128 + row * 32);
        int4* pl = reinterpret_cast<int4*>(sm + OFF_ALO + 128 + row * 32);
        ph[0] = z4; ph[1] = z4;
        pl[0] = z4; pl[1] = z4;
    }
    if (tid < 16) {
        int4* g = reinterpret_cast<int4*>(
            sm + (tid < 8 ? OFF_AHI : OFF_ALO) + (tid & 7) * 16);
        g[0] = z4;
    }
    {
        const int4* src = reinterpret_cast<const int4*>(g_wp);
        int4* dst = reinterpret_cast<int4*>(sm + OFF_W);
        for (int j = tid; j < 3200; j += NTHREADS) dst[j] = src[j];
    }
    if (tid < 32) sBias[tid] = convb[tid];
    if (tid < 256) { // transpose proj to [oc][n]
        int n = tid >> 5, oc = tid & 31;
        sProjT[oc * 8 + n] = projw[tid];
    }
    for (int j = tid; j < L_; j += NTHREADS)
        sMask[j] = (mask[b * L_ + j] != 0) ? 1 : 0;

    // fp32 [ch][px] -> bf16 hi/lo channel-last padded image (interior rows)
    {
        const float* src = g_cum + (size_t)bt * CIN_ * L_;
        for (int px = tid; px < L_; px += NTHREADS) {
            uint32_t h[8], l[8];
            #pragma unroll
            for (int cp = 0; cp < 8; cp++) {
                float v0 = src[(2 * cp) * L_ + px];
                float v1 = src[(2 * cp + 1) * L_ + px];
                __nv_bfloat16 h0 = __float2bfloat16_rn(v0);
                __nv_bfloat16 h1 = __float2bfloat16_rn(v1);
                __nv_bfloat16 l0 = __float2bfloat16_rn(v0 - __bfloat162float(h0));
                __nv_bfloat16 l1 = __float2bfloat16_rn(v1 - __bfloat162float(h1));
                h[cp] = ((uint32_t)*reinterpret_cast<uint16_t*>(&h1) << 16)
                      | (uint32_t)*reinterpret_cast<uint16_t*>(&h0);
                l[cp] = ((uint32_t)*reinterpret_cast<uint16_t*>(&l1) << 16)
                      | (uint32_t)*reinterpret_cast<uint16_t*>(&l0);
            }
            int y = px >> 6, x = px & 63;
            int byteoff = 128 + ((y + 2) * PW_ + x + 2) * 32;
            uint4* dh = reinterpret_cast<uint4*>(sm + OFF_AHI + byteoff);
            uint4* dl = reinterpret_cast<uint4*>(sm + OFF_ALO + byteoff);
            dh[0] = make_uint4(h[0], h[1], h[2], h[3]);
            dh[1] = make_uint4(h[4], h[5], h[6], h[7]);
            dl[0] = make_uint4(l[0], l[1], l[2], l[3]);
            dl[1] = make_uint4(l[4], l[5], l[6], l[7]);
        }
    }
    __syncthreads();

    // ---- per-thread ldmatrix base addresses -------------------------------
    uint32_t aHiBase = sb + OFF_AHI + 64
                     + (uint32_t)(lane & 15) * 32 + (uint32_t)(lane >> 4) * 16;
    uint32_t aLoBase = aHiBase + APLANE;
    // B (x4 non-trans of [oc][ic] rows): {b0,b1} oc-octet0, {b0,b1} oc-octet1
    uint32_t wBase = sb + OFF_W
                   + (uint32_t)((lane & 7) + ((lane >> 4) << 3)) * 32
                   + (uint32_t)((lane >> 3) & 1) * 16;

    // ---- main loop: 23 chunks of M=96 (6 m16 tiles), warp-strided ---------
    #pragma unroll 1
    for (int p = wid; p < 23; p += 12) {
        int q0 = p * 96;
        float c[6][4][4];
        #pragma unroll
        for (int mi = 0; mi < 6; mi++)
            #pragma unroll
            for (int j = 0; j < 4; j++)
                #pragma unroll
                for (int r = 0; r < 4; r++) c[mi][j][r] = 0.f;

        uint32_t ah = aHiBase + (uint32_t)q0 * 32;
        uint32_t al = aLoBase + (uint32_t)q0 * 32;

        #pragma unroll
        for (int ky = 0; ky < 5; ky++) {
            #pragma unroll
            for (int kx = 0; kx < 5; kx++) {
                int k = ky * 5 + kx;
                uint32_t off = (uint32_t)(ky * PW_ + kx) * 32;
                uint32_t bh[2][4], bl[2][4];
                uint32_t wtap = wBase + (uint32_t)k * 1024;
                ldsm4(bh[0], wtap);
                ldsm4(bh[1], wtap + 512);
                ldsm4(bl[0], wtap + 25600);
                ldsm4(bl[1], wtap + 25600 + 512);
                // A double-buffer: load mi+1's fragments before mi's mma
                uint32_t ahi[2][4], alo[2][4];
                ldsm4(ahi[0], ah + off);
                ldsm4(alo[0], al + off);
                #pragma unroll
                for (int mi = 0; mi < 6; mi++) {
                    int cur = mi & 1, nxt = cur ^ 1;
                    if (mi < 5) {
                        ldsm4(ahi[nxt], ah + off + (uint32_t)(mi + 1) * 512);
                        ldsm4(alo[nxt], al + off + (uint32_t)(mi + 1) * 512);
                    }
                    // pass-major: same-accumulator mma distance = 4
                    mma16816(c[mi][0], ahi[cur], bh[0] + 0);
                    mma16816(c[mi][1], ahi[cur], bh[0] + 2);
                    mma16816(c[mi][2], ahi[cur], bh[1] + 0);
                    mma16816(c[mi][3], ahi[cur], bh[1] + 2);
                    mma16816(c[mi][0], alo[cur], bh[0] + 0);
                    mma16816(c[mi][1], alo[cur], bh[0] + 2);
                    mma16816(c[mi][2], alo[cur], bh[1] + 0);
                    mma16816(c[mi][3], alo[cur], bh[1] + 2);
                    mma16816(c[mi][0], ahi[cur], bl[0] + 0);
                    mma16816(c[mi][1], ahi[cur], bl[0] + 2);
                    mma16816(c[mi][2], ahi[cur], bl[1] + 0);
                    mma16816(c[mi][3], ahi[cur], bl[1] + 2);
                }
            }
        }

        // ---- epilogue: bias+relu+proj, quad-reduce, store -----------------
        #pragma unroll
        for (int mi = 0; mi < 6; mi++) {
            #pragma unroll
            for (int half = 0; half < 2; half++) {
                int row = (lane >> 2) + half * 8;
                int q = q0 + mi * 16 + row;
                int y = q / PW_;
                int xe = q - y * PW_;
                bool valid = (xe >= 2 && xe < 66 && y < 32);
                int px = y * 64 + (xe - 2);
                float v[8];
                #pragma unroll
                for (int n = 0; n < 8; n++) v[n] = 0.f;
                if (valid && !sMask[px]) {
                    #pragma unroll
                    for (int j = 0; j < 4; j++) {
                        #pragma unroll
                        for (int e = 0; e < 2; e++) {
                            int oc = 8 * j + (lane & 3) * 2 + e;
                            float rv = fmaxf(c[mi][j][half * 2 + e] + sBias[oc],
                                             0.f);
                            const float* pt = sProjT + oc * 8;
                            #pragma unroll
                            for (int n = 0; n < 8; n++)
                                v[n] = fmaf(pt[n], rv, v[n]);
                        }
                    }
                }
                #pragma unroll
                for (int n = 0; n < 8; n++) {
                    v[n] += __shfl_xor_sync(0xffffffffu, v[n], 1);
                    v[n] += __shfl_xor_sync(0xffffffffu, v[n], 2);
                }
                if (valid) {
                    int n0 = (lane & 3) * 2;
                    size_t o0 = (((size_t)(b * 8 + n0) * T_ + t) << 11) + px;
                    out[o0] = v[n0];
                    out[o0 + ((size_t)T_ << 11)] = v[n0 + 1];
                }
            }
        }
    }
}

// ---------------------------------------------------------------------------
// K2b: per-channel sum/sumsq over stored pre-BN output (masked entries are 0)
// ---------------------------------------------------------------------------
__global__ void sum_kernel(const float* __restrict__ out) {
    __shared__ float sred[2];
    int tid = threadIdx.x;
    int bk  = blockIdx.x;
    int n   = (bk >> 4) & 7;
    if (tid == 0) { sred[0] = 0.f; sred[1] = 0.f; }
    __syncthreads();
    const float4* p = reinterpret_cast<const float4*>(out) + (size_t)bk * 4096;
    float s = 0.f, sq = 0.f;
    for (int i = tid; i < 4096; i += 256) {
        float4 v = p[i];
        s  += v.x + v.y + v.z + v.w;
        sq += v.x * v.x + v.y * v.y + v.z * v.z + v.w * v.w;
    }
    #pragma unroll
    for (int off = 16; off; off >>= 1) {
        s  += __shfl_xor_sync(0xffffffffu, s, off);
        sq += __shfl_xor_sync(0xffffffffu, sq, off);
    }
    if ((tid & 31) == 0) {
        atomicAdd(&sred[0], s);
        atomicAdd(&sred[1], sq);
    }
    __syncthreads();
    if (tid == 0) {
        atomicAdd(&g_acc[n], sred[0]);
        atomicAdd(&g_acc[8 + n], sred[1]);
    }
}

// ---------------------------------------------------------------------------
// K4 BN apply (stats computed inline from g_acc/g_cnt)
// ---------------------------------------------------------------------------
__global__ void bn_apply_kernel(float* __restrict__ out,
                                const int* __restrict__ mask,
                                const float* __restrict__ gamma,
                                const float* __restrict__ beta) {
    int idx = blockIdx.x * 256 + threadIdx.x;
    int nlin = idx >> 16;
    int n = nlin & 7;
    int bb = nlin >> 3;
    int l4 = idx & 511;
    float cnt  = g_cnt;
    float mean = g_acc[n] / cnt;
    float var  = fmaxf(g_acc[8 + n] / cnt - mean * mean, 0.0f);
    float sc   = gamma[n] * rsqrtf(var + 1e-5f);
    float sh   = beta[n] - mean * sc;
    int4 m = *reinterpret_cast<const int4*>(mask + bb * L_ + l4 * 4);
    float4* p = reinterpret_cast<float4*>(out) + idx;
    float4 v = *p;
    v.x = m.x ? v.x : fmaf(v.x, sc, sh);
    v.y = m.y ? v.y : fmaf(v.y, sc, sh);
    v.z = m.z ? v.z : fmaf(v.z, sc, sh);
    v.w = m.w ? v.w : fmaf(v.w, sc, sh);
    *p = v;
}

// ---------------------------------------------------------------------------
extern "C" void kernel_launch(void* const* d_in, const int* in_sizes, int n_in,
                              void* d_out, int out_size) {
    const float* prev  = (const float*)d_in[0];
    const float* curr  = (const float*)d_in[1];
    const int*   mask  = (const int*)d_in[2];
    const float* convw = (const float*)d_in[4];
    const float* convb = (const float*)d_in[5];
    const float* projw = (const float*)d_in[6];
    const float* gamma = (const float*)d_in[7];
    const float* beta  = (const float*)d_in[8];
    float* out = (float*)d_out;

    cudaFuncSetAttribute(conv_kernel,
                         cudaFuncAttributeMaxDynamicSharedMemorySize,
                         SMEM_TOTAL);

    cumsum_kernel<<<257, 256>>>(prev, curr, mask, convw);
    conv_kernel<<<B_ * T_, NTHREADS, SMEM_TOTAL>>>(convb, projw, mask, out);
    sum_kernel<<<1024, 256>>>(out);
    bn_apply_kernel<<<(B_ * NH_ * T_ * L_ / 4) / 256, 256>>>(out, mask,
                                                             gamma, beta);
}